// round 14
// baseline (speedup 1.0000x reference)
#include <cuda_runtime.h>
#include <cuda_fp16.h>
#include <math.h>

#define NN 100000
#define NE 3200000
#define IND 128
#define HID 64
#define NG 256
#define NB 391          // ceil(NN/256) scan blocks

// ---------------- scratch (static device globals; no allocation) ----------------
__device__ int                g_is64;        // 1 if ei/batch int64, 0 if int32
__device__ unsigned long long g_packed[NN];  // [44:64) count, [0:44) fx weighted degree (ew * 2^20)
__device__ float              g_dis[NN];
__device__ int                g_cnt_node[NN];
__device__ int                g_bsum[NB];
__device__ int                g_offs[NN + 1];
__device__ int                g_offs_work[NN];
__device__ int2               g_csr[NE];      // packed {src row, norm bits}
__device__ float4             g_xl4[NN * (HID / 4)];   // fp32 xl (self-loop term)
__device__ uint2              g_xlh[NN * (HID / 4)];   // fp16 xl (gather payload): 2x half2 per uint2
__device__ float4             g_h4[NN * (HID / 4)];
__device__ float4             g_pool4[NG * (HID / 4)];
__device__ float              g_gcnt[NG];

// Explicit global-space vector reduction (16B-aligned dst).
__device__ __forceinline__ void red_add_v4(float4* dst, float4 v) {
    unsigned long long gaddr =
        (unsigned long long)__cvta_generic_to_global((void*)dst);
    asm volatile("red.global.add.v4.f32 [%0], {%1,%2,%3,%4};"
                 :: "l"(gaddr), "f"(v.x), "f"(v.y), "f"(v.z), "f"(v.w)
                 : "memory");
}

// Index load honoring detected dtype.
__device__ __forceinline__ int load_idx(const void* p, long long i) {
    if (g_is64) return (int)((const long long*)p)[i];
    return ((const int*)p)[i];
}

// ---------------- init + dtype detection ----------------
__global__ void k_init(const int* __restrict__ ei_words) {
    int i = blockIdx.x * blockDim.x + threadIdx.x;
    if (i < NN) g_packed[i] = 0ULL;
    if (blockIdx.x == 0 && threadIdx.x == 0) {
        int is64 = 1;
        for (int k = 0; k < 128; k++)
            if (ei_words[2 * k + 1] != 0) { is64 = 0; break; }
        g_is64 = is64;
    }
}

// ---------------- histogram + weighted degree: ONE packed atomic per edge ----
__global__ void k_hist(const void* __restrict__ ei, const float* __restrict__ ew) {
    int e = blockIdx.x * blockDim.x + threadIdx.x;
    if (e < NE) {
        int c = load_idx(ei, (long long)NE + e);
        if ((unsigned)c >= NN) c = 0;
        unsigned int fx = __float2uint_rn(ew[e] * 1048576.0f);  // ew * 2^20
        atomicAdd(&g_packed[c], (1ULL << 44) | (unsigned long long)fx);
    }
}

// ---------------- parallel exclusive scan over 100K counts ----------------
__global__ void __launch_bounds__(256) k_scan_partial() {
    __shared__ int s[256];
    int tid = threadIdx.x;
    int idx = blockIdx.x * 256 + tid;
    int v = 0;
    if (idx < NN) {
        unsigned long long p = g_packed[idx];
        v = (int)(p >> 44);
        float deg = (float)(p & 0xFFFFFFFFFFFULL) * (1.0f / 1048576.0f) + 1.0f;
        g_dis[idx] = rsqrtf(deg);   // deg >= 1 (self-loop weight 1)
        g_cnt_node[idx] = v;
    }
    s[tid] = v;
    __syncthreads();
#pragma unroll
    for (int o = 128; o > 0; o >>= 1) {
        if (tid < o) s[tid] += s[tid + o];
        __syncthreads();
    }
    if (tid == 0) g_bsum[blockIdx.x] = s[0];
}

__global__ void __launch_bounds__(512) k_scan_blocks() {
    __shared__ int s[512];
    int tid = threadIdx.x;
    int v = (tid < NB) ? g_bsum[tid] : 0;
    s[tid] = v;
    __syncthreads();
    for (int d = 1; d < 512; d <<= 1) {
        int t = (tid >= d) ? s[tid - d] : 0;
        __syncthreads();
        s[tid] += t;
        __syncthreads();
    }
    if (tid < NB) g_bsum[tid] = s[tid] - v;   // exclusive
    if (tid == 0) g_offs[NN] = NE;
}

__global__ void __launch_bounds__(256) k_scan_offs() {
    __shared__ int s[256];
    int tid = threadIdx.x;
    int idx = blockIdx.x * 256 + tid;
    int v = (idx < NN) ? g_cnt_node[idx] : 0;
    s[tid] = v;
    __syncthreads();
    for (int d = 1; d < 256; d <<= 1) {
        int t = (tid >= d) ? s[tid - d] : 0;
        __syncthreads();
        s[tid] += t;
        __syncthreads();
    }
    if (idx < NN) {
        int o = g_bsum[blockIdx.x] + s[tid] - v;
        g_offs[idx] = o;
        g_offs_work[idx] = o;
    }
}

// ---------------- permute edges into packed CSR (norm fused) ----------------
__global__ void k_permute(const void* __restrict__ ei, const float* __restrict__ ew) {
    int e = blockIdx.x * blockDim.x + threadIdx.x;
    if (e < NE) {
        int r = load_idx(ei, e);
        int c = load_idx(ei, (long long)NE + e);
        if ((unsigned)r >= NN) r = 0;
        if ((unsigned)c >= NN) c = 0;
        int slot = atomicAdd(&g_offs_work[c], 1);
        float w = g_dis[r] * ew[e] * g_dis[c];
        g_csr[slot] = make_int2(r, __float_as_int(w));
    }
}

// ---------------- tiled GEMM: xl = A[N,K] @ W[K,64], dual fp32+fp16 output ----
// SRC=0: A = Ain (harness input x). SRC=1: A = g_h4 (bound in device code --
// passing __device__ symbols as host args silently hits the host shadow via
// ATS on GB300).
template <int K, int SRC>
__global__ void __launch_bounds__(128) k_mm(const float* __restrict__ Ain,
                                            const float* __restrict__ W) {
    constexpr int SP = K + 4;   // float4-aligned row stride
    constexpr int K4 = K / 4;
    __shared__ float As[64 * SP];
    const float* A = (SRC == 0) ? Ain : (const float*)g_h4;

    int tid = threadIdx.x;
    int row0 = blockIdx.x * 64;
    int rows_in = NN - row0; if (rows_in > 64) rows_in = 64;

    const float4* A4 = (const float4*)A;
    for (int f = tid; f < 64 * K4; f += 128) {
        int r = f / K4, kq = f % K4;
        float4 v = (r < rows_in) ? A4[(row0 + r) * K4 + kq]
                                 : make_float4(0.f, 0.f, 0.f, 0.f);
        *(float4*)&As[r * SP + kq * 4] = v;
    }
    __syncthreads();

    int ty = tid >> 4;
    int tx = tid & 15;
    const float4* W4 = (const float4*)W;
    float4 acc[8];
#pragma unroll
    for (int i = 0; i < 8; i++) acc[i] = make_float4(0.f, 0.f, 0.f, 0.f);

#pragma unroll 2
    for (int kq = 0; kq < K4; kq++) {
        float4 b0 = __ldg(&W4[(4 * kq + 0) * 16 + tx]);
        float4 b1 = __ldg(&W4[(4 * kq + 1) * 16 + tx]);
        float4 b2 = __ldg(&W4[(4 * kq + 2) * 16 + tx]);
        float4 b3 = __ldg(&W4[(4 * kq + 3) * 16 + tx]);
#pragma unroll
        for (int i = 0; i < 8; i++) {
            float4 a = *(const float4*)&As[(ty + 8 * i) * SP + 4 * kq];
            acc[i].x = fmaf(a.x, b0.x, acc[i].x);
            acc[i].y = fmaf(a.x, b0.y, acc[i].y);
            acc[i].z = fmaf(a.x, b0.z, acc[i].z);
            acc[i].w = fmaf(a.x, b0.w, acc[i].w);
            acc[i].x = fmaf(a.y, b1.x, acc[i].x);
            acc[i].y = fmaf(a.y, b1.y, acc[i].y);
            acc[i].z = fmaf(a.y, b1.z, acc[i].z);
            acc[i].w = fmaf(a.y, b1.w, acc[i].w);
            acc[i].x = fmaf(a.z, b2.x, acc[i].x);
            acc[i].y = fmaf(a.z, b2.y, acc[i].y);
            acc[i].z = fmaf(a.z, b2.z, acc[i].z);
            acc[i].w = fmaf(a.z, b2.w, acc[i].w);
            acc[i].x = fmaf(a.w, b3.x, acc[i].x);
            acc[i].y = fmaf(a.w, b3.y, acc[i].y);
            acc[i].z = fmaf(a.w, b3.z, acc[i].z);
            acc[i].w = fmaf(a.w, b3.w, acc[i].w);
        }
    }
#pragma unroll
    for (int i = 0; i < 8; i++) {
        int r = ty + 8 * i;
        if (r < rows_in) {
            g_xl4[(row0 + r) * 16 + tx] = acc[i];
            __half2 lo = __floats2half2_rn(acc[i].x, acc[i].y);
            __half2 hi = __floats2half2_rn(acc[i].z, acc[i].w);
            g_xlh[(row0 + r) * 16 + tx] =
                make_uint2(*(unsigned*)&lo, *(unsigned*)&hi);
        }
    }
}

// ---------------- warp-per-node CSR aggregation (fp16 gather), fused epilogue --
// h[n] = relu( sum_e w_e * xl_h16[src_e] + dis[n]^2 * xl_f32[n] + b )
// FUSE_POOL=0: write to g_h4. FUSE_POOL=1: red into g_pool4[batch[n]] instead.
template <int FUSE_POOL>
__global__ void __launch_bounds__(256) k_agg(const float* __restrict__ bias,
                                             const void* __restrict__ batch) {
    int warp = (blockIdx.x * blockDim.x + threadIdx.x) >> 5;
    if (warp >= NN) return;
    int lane = threadIdx.x & 31;
    int q = lane & 15;      // 4-feature chunk of the 64-wide feature
    int sub = lane >> 4;    // which of 2 edges in flight
    int n = warp;
    int start = g_offs[n], end = g_offs[n + 1];

    float4 acc = make_float4(0.f, 0.f, 0.f, 0.f);
#pragma unroll 4
    for (int i = start + sub; i < end; i += 2) {
        int2 ed = g_csr[i];
        int r = ed.x;
        float w = __int_as_float(ed.y);
        uint2 hv = g_xlh[r * 16 + q];            // 4 halves = 8B
        float2 lo = __half22float2(*(__half2*)&hv.x);
        float2 hi = __half22float2(*(__half2*)&hv.y);
        acc.x = fmaf(w, lo.x, acc.x);
        acc.y = fmaf(w, lo.y, acc.y);
        acc.z = fmaf(w, hi.x, acc.z);
        acc.w = fmaf(w, hi.y, acc.w);
    }
    acc.x += __shfl_xor_sync(0xffffffff, acc.x, 16);
    acc.y += __shfl_xor_sync(0xffffffff, acc.y, 16);
    acc.z += __shfl_xor_sync(0xffffffff, acc.z, 16);
    acc.w += __shfl_xor_sync(0xffffffff, acc.w, 16);

    if (sub == 0) {
        float d = g_dis[n];
        float d2 = d * d;
        float4 sv = g_xl4[n * 16 + q];           // self term from fp32 copy
        float4 b4 = ((const float4*)bias)[q];
        float4 res;
        res.x = fmaxf(fmaf(d2, sv.x, acc.x) + b4.x, 0.f);
        res.y = fmaxf(fmaf(d2, sv.y, acc.y) + b4.y, 0.f);
        res.z = fmaxf(fmaf(d2, sv.z, acc.z) + b4.z, 0.f);
        res.w = fmaxf(fmaf(d2, sv.w, acc.w) + b4.w, 0.f);
        if (FUSE_POOL) {
            int g = load_idx(batch, n);
            if ((unsigned)g >= NG) g = 0;
            red_add_v4(&g_pool4[g * 16 + q], res);
            if (lane == 0) atomicAdd(&g_gcnt[g], 1.0f);
        } else {
            g_h4[n * 16 + q] = res;
        }
    }
}

// ---------------- zero pool ----------------
__global__ void k_zero_pool() {
    int t = blockIdx.x * blockDim.x + threadIdx.x;
    if (t < NG * (HID / 4))
        g_pool4[t] = make_float4(0.f, 0.f, 0.f, 0.f);
    if (t < NG) g_gcnt[t] = 0.f;
}

// ---------------- classifier head ----------------
__global__ void k_final(const float* __restrict__ Wc, const float* __restrict__ bc,
                        float* __restrict__ out) {
    int g = blockIdx.x;
    int j = threadIdx.x;
    __shared__ float s[HID];
    const float* pool = (const float*)g_pool4;
    float c = fmaxf(g_gcnt[g], 1.0f);
    s[j] = pool[g * HID + j] / c * Wc[j];
    __syncthreads();
#pragma unroll
    for (int o = 32; o > 0; o >>= 1) {
        if (j < o) s[j] += s[j + o];
        __syncthreads();
    }
    if (j == 0) out[g] = s[0] + bc[0];
}

// ---------------- launch ----------------
extern "C" void kernel_launch(void* const* d_in, const int* in_sizes, int n_in,
                              void* d_out, int out_size) {
    const float* x     = (const float*)d_in[0];
    const void*  ei    = d_in[1];
    const float* ew    = (const float*)d_in[2];
    const void*  batch = d_in[3];
    const float* W1    = (const float*)d_in[4];
    const float* b1    = (const float*)d_in[5];
    const float* W2    = (const float*)d_in[6];
    const float* b2    = (const float*)d_in[7];
    const float* Wc    = (const float*)d_in[8];
    const float* bc    = (const float*)d_in[9];
    float*       out   = (float*)d_out;

    // Lazily-created side stream + events (objects cached; identical launch
    // pattern every call -> deterministic, graph-capturable fork/join).
    static cudaStream_t s_side = nullptr;
    static cudaEvent_t  ev_fork = nullptr, ev_join = nullptr;
    if (s_side == nullptr) {
        cudaStreamCreateWithFlags(&s_side, cudaStreamNonBlocking);
        cudaEventCreateWithFlags(&ev_fork, cudaEventDisableTiming);
        cudaEventCreateWithFlags(&ev_join, cudaEventDisableTiming);
    }

    const int T = 256;

    // ---- fork: mm1 (x@W1) + pool zeroing run parallel to the CSR build ----
    cudaEventRecord(ev_fork, 0);
    cudaStreamWaitEvent(s_side, ev_fork, 0);
    k_mm<IND, 0><<<(NN + 63) / 64, 128, 0, s_side>>>(x, W1);
    k_zero_pool<<<(NG * HID + T - 1) / T, T, 0, s_side>>>();
    cudaEventRecord(ev_join, s_side);

    // ---- main stream: CSR + normalization precompute ----
    k_init<<<(NN + T - 1) / T, T>>>((const int*)ei);
    k_hist<<<(NE + T - 1) / T, T>>>(ei, ew);
    k_scan_partial<<<NB, 256>>>();
    k_scan_blocks<<<1, 512>>>();
    k_scan_offs<<<NB, 256>>>();
    k_permute<<<(NE + T - 1) / T, T>>>(ei, ew);

    // ---- join, then the dependent chain ----
    cudaStreamWaitEvent(0, ev_join, 0);
    k_agg<0><<<(NN * 32 + T - 1) / T, T>>>(b1, batch);
    k_mm<HID, 1><<<(NN + 63) / 64, 128>>>(nullptr, W2);
    k_agg<1><<<(NN * 32 + T - 1) / T, T>>>(b2, batch);
    k_final<<<NG, HID>>>(Wc, bc, out);
}

// round 15
// speedup vs baseline: 1.4117x; 1.4117x over previous
#include <cuda_runtime.h>
#include <cuda_fp16.h>
#include <math.h>

#define NN 100000
#define NE 3200000
#define IND 128
#define HID 64
#define NG 256
#define NB 391          // ceil(NN/256) scan blocks

// ---------------- scratch (static device globals; no allocation) ----------------
__device__ int                g_is64;        // 1 if ei/batch int64, 0 if int32
__device__ unsigned long long g_packed[NN];  // [44:64) count, [0:44) fx weighted degree (ew * 2^20)
__device__ float              g_dis[NN];
__device__ int                g_cnt_node[NN];
__device__ int                g_bsum[NB];
__device__ int                g_offs[NN + 1];
__device__ int                g_offs_work[NN];
__device__ int2               g_csr[NE];      // packed {src row, norm bits}
__device__ uint2              g_xlh[NN * (HID / 4)];  // fp16 xl: 2x half2 per uint2 (ONLY xl copy)
__device__ float4             g_h4[NN * (HID / 4)];   // fp32 hidden state (layer 1)
__device__ float4             g_pool4[NG * (HID / 4)];
__device__ float              g_gcnt[NG];

// Explicit global-space vector reduction (16B-aligned dst).
__device__ __forceinline__ void red_add_v4(float4* dst, float4 v) {
    unsigned long long gaddr =
        (unsigned long long)__cvta_generic_to_global((void*)dst);
    asm volatile("red.global.add.v4.f32 [%0], {%1,%2,%3,%4};"
                 :: "l"(gaddr), "f"(v.x), "f"(v.y), "f"(v.z), "f"(v.w)
                 : "memory");
}

// Index load honoring detected dtype.
__device__ __forceinline__ int load_idx(const void* p, long long i) {
    if (g_is64) return (int)((const long long*)p)[i];
    return ((const int*)p)[i];
}

// ---------------- init + dtype detection ----------------
__global__ void k_init(const int* __restrict__ ei_words) {
    int i = blockIdx.x * blockDim.x + threadIdx.x;
    if (i < NN) g_packed[i] = 0ULL;
    if (blockIdx.x == 0 && threadIdx.x == 0) {
        int is64 = 1;
        for (int k = 0; k < 128; k++)
            if (ei_words[2 * k + 1] != 0) { is64 = 0; break; }
        g_is64 = is64;
    }
}

// ---------------- histogram + weighted degree: ONE packed atomic per edge ----
__global__ void k_hist(const void* __restrict__ ei, const float* __restrict__ ew) {
    int e = blockIdx.x * blockDim.x + threadIdx.x;
    if (e < NE) {
        int c = load_idx(ei, (long long)NE + e);
        if ((unsigned)c >= NN) c = 0;
        unsigned int fx = __float2uint_rn(ew[e] * 1048576.0f);  // ew * 2^20
        atomicAdd(&g_packed[c], (1ULL << 44) | (unsigned long long)fx);
    }
}

// ---------------- parallel exclusive scan over 100K counts ----------------
__global__ void __launch_bounds__(256) k_scan_partial() {
    __shared__ int s[256];
    int tid = threadIdx.x;
    int idx = blockIdx.x * 256 + tid;
    int v = 0;
    if (idx < NN) {
        unsigned long long p = g_packed[idx];
        v = (int)(p >> 44);
        float deg = (float)(p & 0xFFFFFFFFFFFULL) * (1.0f / 1048576.0f) + 1.0f;
        g_dis[idx] = rsqrtf(deg);   // deg >= 1 (self-loop weight 1)
        g_cnt_node[idx] = v;
    }
    s[tid] = v;
    __syncthreads();
#pragma unroll
    for (int o = 128; o > 0; o >>= 1) {
        if (tid < o) s[tid] += s[tid + o];
        __syncthreads();
    }
    if (tid == 0) g_bsum[blockIdx.x] = s[0];
}

__global__ void __launch_bounds__(512) k_scan_blocks() {
    __shared__ int s[512];
    int tid = threadIdx.x;
    int v = (tid < NB) ? g_bsum[tid] : 0;
    s[tid] = v;
    __syncthreads();
    for (int d = 1; d < 512; d <<= 1) {
        int t = (tid >= d) ? s[tid - d] : 0;
        __syncthreads();
        s[tid] += t;
        __syncthreads();
    }
    if (tid < NB) g_bsum[tid] = s[tid] - v;   // exclusive
    if (tid == 0) g_offs[NN] = NE;
}

__global__ void __launch_bounds__(256) k_scan_offs() {
    __shared__ int s[256];
    int tid = threadIdx.x;
    int idx = blockIdx.x * 256 + tid;
    int v = (idx < NN) ? g_cnt_node[idx] : 0;
    s[tid] = v;
    __syncthreads();
    for (int d = 1; d < 256; d <<= 1) {
        int t = (tid >= d) ? s[tid - d] : 0;
        __syncthreads();
        s[tid] += t;
        __syncthreads();
    }
    if (idx < NN) {
        int o = g_bsum[blockIdx.x] + s[tid] - v;
        g_offs[idx] = o;
        g_offs_work[idx] = o;
    }
}

// ---------------- permute edges into packed CSR (norm fused) ----------------
__global__ void k_permute(const void* __restrict__ ei, const float* __restrict__ ew) {
    int e = blockIdx.x * blockDim.x + threadIdx.x;
    if (e < NE) {
        int r = load_idx(ei, e);
        int c = load_idx(ei, (long long)NE + e);
        if ((unsigned)r >= NN) r = 0;
        if ((unsigned)c >= NN) c = 0;
        int slot = atomicAdd(&g_offs_work[c], 1);
        float w = g_dis[r] * ew[e] * g_dis[c];
        g_csr[slot] = make_int2(r, __float_as_int(w));
    }
}

// ---------------- tiled GEMM: xl = A[N,K] @ W[K,64], fp16 output ONLY --------
// SRC=0: A = Ain (harness input x). SRC=1: A = g_h4 (bound in device code --
// passing __device__ symbols as host args silently hits the host shadow via
// ATS on GB300). Accumulation fp32; single fp16 store (12.8MB total).
template <int K, int SRC>
__global__ void __launch_bounds__(128) k_mm(const float* __restrict__ Ain,
                                            const float* __restrict__ W) {
    constexpr int SP = K + 4;   // float4-aligned row stride
    constexpr int K4 = K / 4;
    __shared__ float As[64 * SP];
    const float* A = (SRC == 0) ? Ain : (const float*)g_h4;

    int tid = threadIdx.x;
    int row0 = blockIdx.x * 64;
    int rows_in = NN - row0; if (rows_in > 64) rows_in = 64;

    const float4* A4 = (const float4*)A;
    for (int f = tid; f < 64 * K4; f += 128) {
        int r = f / K4, kq = f % K4;
        float4 v = (r < rows_in) ? A4[(row0 + r) * K4 + kq]
                                 : make_float4(0.f, 0.f, 0.f, 0.f);
        *(float4*)&As[r * SP + kq * 4] = v;
    }
    __syncthreads();

    int ty = tid >> 4;
    int tx = tid & 15;
    const float4* W4 = (const float4*)W;
    float4 acc[8];
#pragma unroll
    for (int i = 0; i < 8; i++) acc[i] = make_float4(0.f, 0.f, 0.f, 0.f);

#pragma unroll 2
    for (int kq = 0; kq < K4; kq++) {
        float4 b0 = __ldg(&W4[(4 * kq + 0) * 16 + tx]);
        float4 b1 = __ldg(&W4[(4 * kq + 1) * 16 + tx]);
        float4 b2 = __ldg(&W4[(4 * kq + 2) * 16 + tx]);
        float4 b3 = __ldg(&W4[(4 * kq + 3) * 16 + tx]);
#pragma unroll
        for (int i = 0; i < 8; i++) {
            float4 a = *(const float4*)&As[(ty + 8 * i) * SP + 4 * kq];
            acc[i].x = fmaf(a.x, b0.x, acc[i].x);
            acc[i].y = fmaf(a.x, b0.y, acc[i].y);
            acc[i].z = fmaf(a.x, b0.z, acc[i].z);
            acc[i].w = fmaf(a.x, b0.w, acc[i].w);
            acc[i].x = fmaf(a.y, b1.x, acc[i].x);
            acc[i].y = fmaf(a.y, b1.y, acc[i].y);
            acc[i].z = fmaf(a.y, b1.z, acc[i].z);
            acc[i].w = fmaf(a.y, b1.w, acc[i].w);
            acc[i].x = fmaf(a.z, b2.x, acc[i].x);
            acc[i].y = fmaf(a.z, b2.y, acc[i].y);
            acc[i].z = fmaf(a.z, b2.z, acc[i].z);
            acc[i].w = fmaf(a.z, b2.w, acc[i].w);
            acc[i].x = fmaf(a.w, b3.x, acc[i].x);
            acc[i].y = fmaf(a.w, b3.y, acc[i].y);
            acc[i].z = fmaf(a.w, b3.z, acc[i].z);
            acc[i].w = fmaf(a.w, b3.w, acc[i].w);
        }
    }
#pragma unroll
    for (int i = 0; i < 8; i++) {
        int r = ty + 8 * i;
        if (r < rows_in) {
            __half2 lo = __floats2half2_rn(acc[i].x, acc[i].y);
            __half2 hi = __floats2half2_rn(acc[i].z, acc[i].w);
            g_xlh[(row0 + r) * 16 + tx] =
                make_uint2(*(unsigned*)&lo, *(unsigned*)&hi);
        }
    }
}

// ---------------- warp-per-node CSR aggregation (all-fp16 xl), fused epilogue --
// h[n] = relu( sum_e w_e * xl16[src_e] + dis[n]^2 * xl16[n] + b ), fp32 accum.
// FUSE_POOL=0: write to g_h4. FUSE_POOL=1: red into g_pool4[batch[n]] instead.
template <int FUSE_POOL>
__global__ void __launch_bounds__(256) k_agg(const float* __restrict__ bias,
                                             const void* __restrict__ batch) {
    int warp = (blockIdx.x * blockDim.x + threadIdx.x) >> 5;
    if (warp >= NN) return;
    int lane = threadIdx.x & 31;
    int q = lane & 15;      // 4-feature chunk of the 64-wide feature
    int sub = lane >> 4;    // which of 2 edges in flight
    int n = warp;
    int start = g_offs[n], end = g_offs[n + 1];

    float4 acc = make_float4(0.f, 0.f, 0.f, 0.f);
#pragma unroll 4
    for (int i = start + sub; i < end; i += 2) {
        int2 ed = g_csr[i];
        int r = ed.x;
        float w = __int_as_float(ed.y);
        uint2 hv = g_xlh[r * 16 + q];            // 4 halves = 8B
        float2 lo = __half22float2(*(__half2*)&hv.x);
        float2 hi = __half22float2(*(__half2*)&hv.y);
        acc.x = fmaf(w, lo.x, acc.x);
        acc.y = fmaf(w, lo.y, acc.y);
        acc.z = fmaf(w, hi.x, acc.z);
        acc.w = fmaf(w, hi.y, acc.w);
    }
    acc.x += __shfl_xor_sync(0xffffffff, acc.x, 16);
    acc.y += __shfl_xor_sync(0xffffffff, acc.y, 16);
    acc.z += __shfl_xor_sync(0xffffffff, acc.z, 16);
    acc.w += __shfl_xor_sync(0xffffffff, acc.w, 16);

    if (sub == 0) {
        float d = g_dis[n];
        float d2 = d * d;
        uint2 sh = g_xlh[n * 16 + q];            // self term (fp16 copy)
        float2 slo = __half22float2(*(__half2*)&sh.x);
        float2 shi = __half22float2(*(__half2*)&sh.y);
        float4 b4 = ((const float4*)bias)[q];
        float4 res;
        res.x = fmaxf(fmaf(d2, slo.x, acc.x) + b4.x, 0.f);
        res.y = fmaxf(fmaf(d2, slo.y, acc.y) + b4.y, 0.f);
        res.z = fmaxf(fmaf(d2, shi.x, acc.z) + b4.z, 0.f);
        res.w = fmaxf(fmaf(d2, shi.y, acc.w) + b4.w, 0.f);
        if (FUSE_POOL) {
            int g = load_idx(batch, n);
            if ((unsigned)g >= NG) g = 0;
            red_add_v4(&g_pool4[g * 16 + q], res);
            if (lane == 0) atomicAdd(&g_gcnt[g], 1.0f);
        } else {
            g_h4[n * 16 + q] = res;
        }
    }
}

// ---------------- zero pool ----------------
__global__ void k_zero_pool() {
    int t = blockIdx.x * blockDim.x + threadIdx.x;
    if (t < NG * (HID / 4))
        g_pool4[t] = make_float4(0.f, 0.f, 0.f, 0.f);
    if (t < NG) g_gcnt[t] = 0.f;
}

// ---------------- classifier head ----------------
__global__ void k_final(const float* __restrict__ Wc, const float* __restrict__ bc,
                        float* __restrict__ out) {
    int g = blockIdx.x;
    int j = threadIdx.x;
    __shared__ float s[HID];
    const float* pool = (const float*)g_pool4;
    float c = fmaxf(g_gcnt[g], 1.0f);
    s[j] = pool[g * HID + j] / c * Wc[j];
    __syncthreads();
#pragma unroll
    for (int o = 32; o > 0; o >>= 1) {
        if (j < o) s[j] += s[j + o];
        __syncthreads();
    }
    if (j == 0) out[g] = s[0] + bc[0];
}

// ---------------- launch ----------------
extern "C" void kernel_launch(void* const* d_in, const int* in_sizes, int n_in,
                              void* d_out, int out_size) {
    const float* x     = (const float*)d_in[0];
    const void*  ei    = d_in[1];
    const float* ew    = (const float*)d_in[2];
    const void*  batch = d_in[3];
    const float* W1    = (const float*)d_in[4];
    const float* b1    = (const float*)d_in[5];
    const float* W2    = (const float*)d_in[6];
    const float* b2    = (const float*)d_in[7];
    const float* Wc    = (const float*)d_in[8];
    const float* bc    = (const float*)d_in[9];
    float*       out   = (float*)d_out;

    // Lazily-created side stream + events (objects cached; identical launch
    // pattern every call -> deterministic, graph-capturable fork/join).
    static cudaStream_t s_side = nullptr;
    static cudaEvent_t  ev_fork = nullptr, ev_join = nullptr;
    if (s_side == nullptr) {
        cudaStreamCreateWithFlags(&s_side, cudaStreamNonBlocking);
        cudaEventCreateWithFlags(&ev_fork, cudaEventDisableTiming);
        cudaEventCreateWithFlags(&ev_join, cudaEventDisableTiming);
    }

    const int T = 256;

    // ---- fork: mm1 (x@W1) + pool zeroing run parallel to the CSR build ----
    cudaEventRecord(ev_fork, 0);
    cudaStreamWaitEvent(s_side, ev_fork, 0);
    k_mm<IND, 0><<<(NN + 63) / 64, 128, 0, s_side>>>(x, W1);
    k_zero_pool<<<(NG * HID + T - 1) / T, T, 0, s_side>>>();
    cudaEventRecord(ev_join, s_side);

    // ---- main stream: CSR + normalization precompute ----
    k_init<<<(NN + T - 1) / T, T>>>((const int*)ei);
    k_hist<<<(NE + T - 1) / T, T>>>(ei, ew);
    k_scan_partial<<<NB, 256>>>();
    k_scan_blocks<<<1, 512>>>();
    k_scan_offs<<<NB, 256>>>();
    k_permute<<<(NE + T - 1) / T, T>>>(ei, ew);

    // ---- join, then the dependent chain ----
    cudaStreamWaitEvent(0, ev_join, 0);
    k_agg<0><<<(NN * 32 + T - 1) / T, T>>>(b1, batch);
    k_mm<HID, 1><<<(NN + 63) / 64, 128>>>(nullptr, W2);
    k_agg<1><<<(NN * 32 + T - 1) / T, T>>>(b2, batch);
    k_final<<<NG, HID>>>(Wc, bc, out);
}